// round 10
// baseline (speedup 1.0000x reference)
#include <cuda_runtime.h>

// ---------------------------------------------------------------------------
// SSIM loss, single fused kernel, R9:
//   - halo: interior fast path (no div/reflect, coalesced), border slow path
//   - horizontal: 8-output streamed tasks (18x LDS.64 per 8 outputs, ring
//     accumulation into 8+8 packed f32x2 accumulators) -> 2.25 reads/output
//   - channels: (mu1,mu2) and (a^2+b^2, a*b), both packed f32x2
//   - vertical: 2 packed passes over 8-row strips (128 threads)
//   - 128-slot double atomics + last-block-done finalize (self-resetting)
// ---------------------------------------------------------------------------

typedef unsigned long long u64;

#define IMGW 512
#define IMGH 512
#define TW   32
#define TH   32
#define HALO 5
#define HW   42
#define SW2  45              // padded smem row stride (u64 units, odd)
#define HR   42
#define NTHREADS 256
#define GX 16
#define GY 16
#define GZ 48
#define NBLOCKS (GX * GY * GZ)
#define NSLOT 128
#define NTASK (HR * 4)       // 168 horizontal tasks (8 outputs each)

#define W0 0.00102838f
#define W1 0.00759876f
#define W2 0.03600077f
#define W3 0.10936069f
#define W4 0.21300554f
#define W5 0.26601173f

__device__ double   g_slots[NSLOT];
__device__ unsigned g_count;

__device__ __forceinline__ int reflect_idx(int i, int n) {
    if (i < 0) i = -i;
    if (i >= n) i = 2 * n - 2 - i;
    return i;
}

__device__ __forceinline__ constexpr int WI(int k) { return (k < 6) ? k : 10 - k; }

// ---- packed f32x2 helpers ----
__device__ __forceinline__ u64 pack2(float x, float y) {
    u64 r;
    asm("mov.b64 %0, {%1, %2};" : "=l"(r) : "f"(x), "f"(y));
    return r;
}
__device__ __forceinline__ void unpack2(u64 v, float& x, float& y) {
    asm("mov.b64 {%0, %1}, %2;" : "=f"(x), "=f"(y) : "l"(v));
}
__device__ __forceinline__ void fma2(u64& d, u64 a, u64 b) {
    asm("fma.rn.f32x2 %0, %1, %2, %0;" : "+l"(d) : "l"(a), "l"(b));
}

__global__ __launch_bounds__(NTHREADS, 5)
void ssim_fused_kernel(const float* __restrict__ img1,
                       const float* __restrict__ img2,
                       float* __restrict__ out) {
    __shared__ u64 s12[HR * SW2];        // interleaved (a,b): 16200 B
    __shared__ u64 hb12[HR * TW];        // (mu1,mu2) h-blur: 10752 B
    __shared__ u64 hbsa[HR * TW];        // (a^2+b^2, a*b) h-blur: 10752 B
    __shared__ float ws[NTHREADS / 32];
    __shared__ double dsum[4];
    __shared__ int s_isLast;

    const int tid = threadIdx.x;
    const int img = blockIdx.z;
    const int tx0 = blockIdx.x * TW;
    const int ty0 = blockIdx.y * TH;

    const float* a = img1 + (size_t)img * (IMGW * IMGH);
    const float* b = img2 + (size_t)img * (IMGW * IMGH);

    const u64 wp[6] = { pack2(W0, W0), pack2(W1, W1), pack2(W2, W2),
                        pack2(W3, W3), pack2(W4, W4), pack2(W5, W5) };

    // ---- load halo tile ----
    const bool interior = (blockIdx.x > 0) & (blockIdx.x < GX - 1) &
                          (blockIdx.y > 0) & (blockIdx.y < GY - 1);
    if (interior) {
        const float* pa = a + (ty0 - HALO) * IMGW + (tx0 - HALO);
        const float* pb = b + (ty0 - HALO) * IMGW + (tx0 - HALO);
        const int ct = tid & 31;
        const int rt = tid >> 5;
#pragma unroll
        for (int rr = 0; rr < 6; rr++) {
            int r = rt + rr * 8;
            if (r < HR) {
                int g = r * IMGW + ct;
                int s = r * SW2 + ct;
#pragma unroll
                for (int cc = 0; cc < 2; cc++) {
                    int c = ct + cc * 32;
                    if (c < HW)
                        s12[s + cc * 32] = pack2(pa[g + cc * 32], pb[g + cc * 32]);
                }
            }
        }
    } else {
        for (int idx = tid; idx < HR * HW; idx += NTHREADS) {
            int r = idx / HW;
            int c = idx - r * HW;
            int gy = reflect_idx(ty0 + r - HALO, IMGH);
            int gx = reflect_idx(tx0 + c - HALO, IMGW);
            int g = gy * IMGW + gx;
            s12[r * SW2 + c] = pack2(a[g], b[g]);
        }
    }
    __syncthreads();

    // ---- horizontal pass: 42 rows x 4 groups of 8 outputs = 168 tasks ----
    if (tid < NTASK) {
        const int r  = tid >> 2;
        const int c0 = (tid & 3) << 3;
        const u64* p = s12 + r * SW2 + c0;

        u64 accA[8] = {0, 0, 0, 0, 0, 0, 0, 0};
        u64 accS[8] = {0, 0, 0, 0, 0, 0, 0, 0};
#pragma unroll
        for (int e = 0; e < 18; e++) {
            u64 v = p[e];
            float x, y; unpack2(v, x, y);
            float ab = x * y;
            float ss = fmaf(x, x, y * y);
            u64 sv = pack2(ss, ab);
#pragma unroll
            for (int j = 0; j < 8; j++) {
                int k = e - j;
                if (k >= 0 && k <= 10) {
                    fma2(accA[j], v,  wp[WI(k)]);
                    fma2(accS[j], sv, wp[WI(k)]);
                }
            }
        }
        const int o = r * TW + c0;
        *(ulonglong2*)&hb12[o]     = make_ulonglong2(accA[0], accA[1]);
        *(ulonglong2*)&hb12[o + 2] = make_ulonglong2(accA[2], accA[3]);
        *(ulonglong2*)&hb12[o + 4] = make_ulonglong2(accA[4], accA[5]);
        *(ulonglong2*)&hb12[o + 6] = make_ulonglong2(accA[6], accA[7]);
        *(ulonglong2*)&hbsa[o]     = make_ulonglong2(accS[0], accS[1]);
        *(ulonglong2*)&hbsa[o + 2] = make_ulonglong2(accS[2], accS[3]);
        *(ulonglong2*)&hbsa[o + 4] = make_ulonglong2(accS[4], accS[5]);
        *(ulonglong2*)&hbsa[o + 6] = make_ulonglong2(accS[6], accS[7]);
    }
    __syncthreads();

    // ---- vertical pass + SSIM: 128 threads, 32 cols x 4 strips of 8 rows ----
    float lsum = 0.f;
    const int tx  = tid & 31;
    const int sid = tid >> 5;

    if (sid < 4) {
        const int r0 = sid << 3;         // 0,8,16,24; reads rows r0..r0+17
        float pA[8], pB[8];              // mu1*mu2, mu1^2+mu2^2

        // pass 1: (mu1, mu2)
        {
            u64 m[8] = {0, 0, 0, 0, 0, 0, 0, 0};
            const u64* p = hb12 + r0 * TW + tx;
#pragma unroll
            for (int k = 0; k < 18; k++) {
                u64 h = p[k * TW];
#pragma unroll
                for (int j = 0; j < 8; j++)
                    if (k - j >= 0 && k - j <= 10) fma2(m[j], h, wp[WI(k - j)]);
            }
#pragma unroll
            for (int j = 0; j < 8; j++) {
                float mu1, mu2; unpack2(m[j], mu1, mu2);
                pA[j] = mu1 * mu2;
                pB[j] = fmaf(mu1, mu1, mu2 * mu2);
            }
        }
        // pass 2: (a^2+b^2, a*b) + SSIM epilogue
        {
            u64 m[8] = {0, 0, 0, 0, 0, 0, 0, 0};
            const u64* p = hbsa + r0 * TW + tx;
#pragma unroll
            for (int k = 0; k < 18; k++) {
                u64 h = p[k * TW];
#pragma unroll
                for (int j = 0; j < 8; j++)
                    if (k - j >= 0 && k - j <= 10) fma2(m[j], h, wp[WI(k - j)]);
            }
            const float C1 = 1e-4f;
            const float C2 = 9e-4f;
#pragma unroll
            for (int j = 0; j < 8; j++) {
                float ssb, e12; unpack2(m[j], ssb, e12);
                float mu12 = pA[j];
                float sg12 = e12 - mu12;
                float num = fmaf(2.f, mu12, C1) * fmaf(2.f, sg12, C2);
                float den = (pB[j] + C1) * (ssb - pB[j] + C2);
                float v = __fdividef(num, den);
                v = fminf(fmaxf(v, 0.f), 1.f);
                lsum += v;
            }
        }
    }

    // ---- block reduction ----
#pragma unroll
    for (int off = 16; off > 0; off >>= 1)
        lsum += __shfl_xor_sync(0xffffffff, lsum, off);
    if ((tid & 31) == 0) ws[tid >> 5] = lsum;
    __syncthreads();

    if (tid == 0) {
        float s = 0.f;
#pragma unroll
        for (int i = 0; i < NTHREADS / 32; i++) s += ws[i];
        const int bid = blockIdx.x + GX * (blockIdx.y + GY * blockIdx.z);
        atomicAdd(&g_slots[bid & (NSLOT - 1)], (double)s);
        __threadfence();
        unsigned old = atomicAdd(&g_count, 1u);
        s_isLast = (old == NBLOCKS - 1);
    }
    __syncthreads();

    // ---- last block: finalize + reset for next graph replay ----
    if (s_isLast) {
        double v = 0.0;
        if (tid < NSLOT) v = ((volatile double*)g_slots)[tid];
#pragma unroll
        for (int off = 16; off > 0; off >>= 1)
            v += __shfl_xor_sync(0xffffffff, v, off);
        if (tid < NSLOT && (tid & 31) == 0) dsum[tid >> 5] = v;
        __syncthreads();
        if (tid == 0) {
            double total = dsum[0] + dsum[1] + dsum[2] + dsum[3];
            const double npix = 16.0 * 3.0 * 512.0 * 512.0;
            out[0] = (float)(1.0 - total / npix);
            g_count = 0;
        }
        if (tid < NSLOT) g_slots[tid] = 0.0;
    }
}

extern "C" void kernel_launch(void* const* d_in, const int* in_sizes, int n_in,
                              void* d_out, int out_size) {
    const float* img1 = (const float*)d_in[0];
    const float* img2 = (const float*)d_in[1];
    float* out = (float*)d_out;

    dim3 grid(GX, GY, GZ);
    ssim_fused_kernel<<<grid, NTHREADS>>>(img1, img2, out);
}

// round 15
// speedup vs baseline: 1.1934x; 1.1934x over previous
#include <cuda_runtime.h>

// ---------------------------------------------------------------------------
// SSIM loss, single fused kernel, R14 (= R11 with alignment fix):
//   - halo: interior fast path (no div/reflect, coalesced), border slow path
//   - horizontal: 8-output streamed tasks (18 LDS.64 per 8 outputs, 2.25x
//     read redundancy), conflict-free lane mapping (7 rows x 4 col-groups
//     per warp, col-group split across half-warps)
//   - hb buffers stride 33 u64 (odd) -> conflict-free banks; stores are
//     STS.64 (u64) because odd stride breaks 16B alignment for STS.128
//   - channels: (mu1,mu2) and (a^2+b^2, a*b), packed f32x2 (FFMA2)
//   - vertical: 2 packed passes over 8-row strips (128 threads)
//   - 128-slot double atomics + last-block-done finalize (self-resetting)
// ---------------------------------------------------------------------------

typedef unsigned long long u64;

#define IMGW 512
#define IMGH 512
#define TW   32
#define TH   32
#define HALO 5
#define HW   42
#define SW2  45              // s12 row stride (u64, odd)
#define HBW  33              // hb row stride (u64, odd)
#define HR   42
#define NTHREADS 256
#define GX 16
#define GY 16
#define GZ 48
#define NBLOCKS (GX * GY * GZ)
#define NSLOT 128

#define W0 0.00102838f
#define W1 0.00759876f
#define W2 0.03600077f
#define W3 0.10936069f
#define W4 0.21300554f
#define W5 0.26601173f

__device__ double   g_slots[NSLOT];
__device__ unsigned g_count;

__device__ __forceinline__ int reflect_idx(int i, int n) {
    if (i < 0) i = -i;
    if (i >= n) i = 2 * n - 2 - i;
    return i;
}

__device__ __forceinline__ constexpr int WI(int k) { return (k < 6) ? k : 10 - k; }

// ---- packed f32x2 helpers ----
__device__ __forceinline__ u64 pack2(float x, float y) {
    u64 r;
    asm("mov.b64 %0, {%1, %2};" : "=l"(r) : "f"(x), "f"(y));
    return r;
}
__device__ __forceinline__ void unpack2(u64 v, float& x, float& y) {
    asm("mov.b64 {%0, %1}, %2;" : "=f"(x), "=f"(y) : "l"(v));
}
__device__ __forceinline__ void fma2(u64& d, u64 a, u64 b) {
    asm("fma.rn.f32x2 %0, %1, %2, %0;" : "+l"(d) : "l"(a), "l"(b));
}

__global__ __launch_bounds__(NTHREADS, 5)
void ssim_fused_kernel(const float* __restrict__ img1,
                       const float* __restrict__ img2,
                       float* __restrict__ out) {
    __shared__ u64 s12[HR * SW2];        // interleaved (a,b): 16200 B
    __shared__ u64 hb12[HR * HBW];       // (mu1,mu2) h-blur: 11088 B
    __shared__ u64 hbsa[HR * HBW];       // (a^2+b^2, a*b) h-blur: 11088 B
    __shared__ float ws[NTHREADS / 32];
    __shared__ double dsum[4];
    __shared__ int s_isLast;

    const int tid = threadIdx.x;
    const int img = blockIdx.z;
    const int tx0 = blockIdx.x * TW;
    const int ty0 = blockIdx.y * TH;

    const float* a = img1 + (size_t)img * (IMGW * IMGH);
    const float* b = img2 + (size_t)img * (IMGW * IMGH);

    const u64 wp[6] = { pack2(W0, W0), pack2(W1, W1), pack2(W2, W2),
                        pack2(W3, W3), pack2(W4, W4), pack2(W5, W5) };

    // ---- load halo tile ----
    const bool interior = (blockIdx.x > 0) & (blockIdx.x < GX - 1) &
                          (blockIdx.y > 0) & (blockIdx.y < GY - 1);
    if (interior) {
        const float* pa = a + (ty0 - HALO) * IMGW + (tx0 - HALO);
        const float* pb = b + (ty0 - HALO) * IMGW + (tx0 - HALO);
        const int ct = tid & 31;
        const int rt = tid >> 5;
#pragma unroll
        for (int rr = 0; rr < 6; rr++) {
            int r = rt + rr * 8;
            if (r < HR) {
                int g = r * IMGW + ct;
                int s = r * SW2 + ct;
#pragma unroll
                for (int cc = 0; cc < 2; cc++) {
                    int c = ct + cc * 32;
                    if (c < HW)
                        s12[s + cc * 32] = pack2(pa[g + cc * 32], pb[g + cc * 32]);
                }
            }
        }
    } else {
        for (int idx = tid; idx < HR * HW; idx += NTHREADS) {
            int r = idx / HW;
            int c = idx - r * HW;
            int gy = reflect_idx(ty0 + r - HALO, IMGH);
            int gx = reflect_idx(tx0 + c - HALO, IMGW);
            int g = gy * IMGW + gx;
            s12[r * SW2 + c] = pack2(a[g], b[g]);
        }
    }
    __syncthreads();

    // ---- horizontal pass: warps 0-5, each 7 rows x 4 col-groups ----
    // lane = c0g_hi<<4 | c0g_lo<<3 | r_local  (half-warp conflict-free)
    {
        const int w    = tid >> 5;
        const int lane = tid & 31;
        const int c0g  = ((lane >> 4) << 1) | ((lane >> 3) & 1);
        const int rl   = lane & 7;
        if (w < 6 && rl < 7) {
            const int r  = w * 7 + rl;        // 0..41
            const int c0 = c0g << 3;          // 0,8,16,24
            const u64* p = s12 + r * SW2 + c0;

            u64 accA[8] = {0, 0, 0, 0, 0, 0, 0, 0};
            u64 accS[8] = {0, 0, 0, 0, 0, 0, 0, 0};
#pragma unroll
            for (int e = 0; e < 18; e++) {
                u64 v = p[e];
                float x, y; unpack2(v, x, y);
                float ab = x * y;
                float ss = fmaf(x, x, y * y);
                u64 sv = pack2(ss, ab);
#pragma unroll
                for (int j = 0; j < 8; j++) {
                    int k = e - j;
                    if (k >= 0 && k <= 10) {
                        fma2(accA[j], v,  wp[WI(k)]);
                        fma2(accS[j], sv, wp[WI(k)]);
                    }
                }
            }
            const int o = r * HBW + c0;
#pragma unroll
            for (int j = 0; j < 8; j++) {
                hb12[o + j] = accA[j];        // STS.64: 8B-aligned always
                hbsa[o + j] = accS[j];
            }
        }
    }
    __syncthreads();

    // ---- vertical pass + SSIM: 128 threads, 32 cols x 4 strips of 8 rows ----
    float lsum = 0.f;
    const int tx  = tid & 31;
    const int sid = tid >> 5;

    if (sid < 4) {
        const int r0 = sid << 3;         // 0,8,16,24; reads rows r0..r0+17
        float pA[8], pB[8];              // mu1*mu2, mu1^2+mu2^2

        // pass 1: (mu1, mu2)
        {
            u64 m[8] = {0, 0, 0, 0, 0, 0, 0, 0};
            const u64* p = hb12 + r0 * HBW + tx;
#pragma unroll
            for (int k = 0; k < 18; k++) {
                u64 h = p[k * HBW];
#pragma unroll
                for (int j = 0; j < 8; j++)
                    if (k - j >= 0 && k - j <= 10) fma2(m[j], h, wp[WI(k - j)]);
            }
#pragma unroll
            for (int j = 0; j < 8; j++) {
                float mu1, mu2; unpack2(m[j], mu1, mu2);
                pA[j] = mu1 * mu2;
                pB[j] = fmaf(mu1, mu1, mu2 * mu2);
            }
        }
        // pass 2: (a^2+b^2, a*b) + SSIM epilogue
        {
            u64 m[8] = {0, 0, 0, 0, 0, 0, 0, 0};
            const u64* p = hbsa + r0 * HBW + tx;
#pragma unroll
            for (int k = 0; k < 18; k++) {
                u64 h = p[k * HBW];
#pragma unroll
                for (int j = 0; j < 8; j++)
                    if (k - j >= 0 && k - j <= 10) fma2(m[j], h, wp[WI(k - j)]);
            }
            const float C1 = 1e-4f;
            const float C2 = 9e-4f;
#pragma unroll
            for (int j = 0; j < 8; j++) {
                float ssb, e12; unpack2(m[j], ssb, e12);
                float mu12 = pA[j];
                float sg12 = e12 - mu12;
                float num = fmaf(2.f, mu12, C1) * fmaf(2.f, sg12, C2);
                float den = (pB[j] + C1) * (ssb - pB[j] + C2);
                float v = __fdividef(num, den);
                v = fminf(fmaxf(v, 0.f), 1.f);
                lsum += v;
            }
        }
    }

    // ---- block reduction ----
#pragma unroll
    for (int off = 16; off > 0; off >>= 1)
        lsum += __shfl_xor_sync(0xffffffff, lsum, off);
    if ((tid & 31) == 0) ws[tid >> 5] = lsum;
    __syncthreads();

    if (tid == 0) {
        float s = 0.f;
#pragma unroll
        for (int i = 0; i < NTHREADS / 32; i++) s += ws[i];
        const int bid = blockIdx.x + GX * (blockIdx.y + GY * blockIdx.z);
        atomicAdd(&g_slots[bid & (NSLOT - 1)], (double)s);
        __threadfence();
        unsigned old = atomicAdd(&g_count, 1u);
        s_isLast = (old == NBLOCKS - 1);
    }
    __syncthreads();

    // ---- last block: finalize + reset for next graph replay ----
    if (s_isLast) {
        double v = 0.0;
        if (tid < NSLOT) v = ((volatile double*)g_slots)[tid];
#pragma unroll
        for (int off = 16; off > 0; off >>= 1)
            v += __shfl_xor_sync(0xffffffff, v, off);
        if (tid < NSLOT && (tid & 31) == 0) dsum[tid >> 5] = v;
        __syncthreads();
        if (tid == 0) {
            double total = dsum[0] + dsum[1] + dsum[2] + dsum[3];
            const double npix = 16.0 * 3.0 * 512.0 * 512.0;
            out[0] = (float)(1.0 - total / npix);
            g_count = 0;
        }
        if (tid < NSLOT) g_slots[tid] = 0.0;
    }
}

extern "C" void kernel_launch(void* const* d_in, const int* in_sizes, int n_in,
                              void* d_out, int out_size) {
    const float* img1 = (const float*)d_in[0];
    const float* img2 = (const float*)d_in[1];
    float* out = (float*)d_out;

    dim3 grid(GX, GY, GZ);
    ssim_fused_kernel<<<grid, NTHREADS>>>(img1, img2, out);
}

// round 16
// speedup vs baseline: 1.2480x; 1.0458x over previous
#include <cuda_runtime.h>

// ---------------------------------------------------------------------------
// SSIM loss, single fused kernel, R16 (= R14 + phase balancing):
//   - halo: interior fast path; border path also div-free (warp-per-row +
//     reflect per index)
//   - horizontal: 8-output streamed tasks on warps 0-5 (conflict-free,
//     2.25x read redundancy), hb stride 33 u64 (odd), STS.64
//   - vertical: channel-split across ALL 8 warps: warps 0-3 blur (mu1,mu2),
//     warps 4-7 blur (a^2+b^2, a*b); mu-side packs (mu12, musq) through
//     scratch (aliased over s12); warps 4-7 run the SSIM epilogue
//   - 128-slot double atomics + last-block-done finalize (self-resetting)
// ---------------------------------------------------------------------------

typedef unsigned long long u64;

#define IMGW 512
#define IMGH 512
#define TW   32
#define TH   32
#define HALO 5
#define HW   42
#define SW2  45              // s12 row stride (u64, odd)
#define HBW  33              // hb row stride (u64, odd)
#define HR   42
#define NTHREADS 256
#define GX 16
#define GY 16
#define GZ 48
#define NBLOCKS (GX * GY * GZ)
#define NSLOT 128

#define W0 0.00102838f
#define W1 0.00759876f
#define W2 0.03600077f
#define W3 0.10936069f
#define W4 0.21300554f
#define W5 0.26601173f

__device__ double   g_slots[NSLOT];
__device__ unsigned g_count;

__device__ __forceinline__ int reflect_idx(int i, int n) {
    if (i < 0) i = -i;
    if (i >= n) i = 2 * n - 2 - i;
    return i;
}

__device__ __forceinline__ constexpr int WI(int k) { return (k < 6) ? k : 10 - k; }

// ---- packed f32x2 helpers ----
__device__ __forceinline__ u64 pack2(float x, float y) {
    u64 r;
    asm("mov.b64 %0, {%1, %2};" : "=l"(r) : "f"(x), "f"(y));
    return r;
}
__device__ __forceinline__ void unpack2(u64 v, float& x, float& y) {
    asm("mov.b64 {%0, %1}, %2;" : "=f"(x), "=f"(y) : "l"(v));
}
__device__ __forceinline__ void fma2(u64& d, u64 a, u64 b) {
    asm("fma.rn.f32x2 %0, %1, %2, %0;" : "+l"(d) : "l"(a), "l"(b));
}

__global__ __launch_bounds__(NTHREADS, 5)
void ssim_fused_kernel(const float* __restrict__ img1,
                       const float* __restrict__ img2,
                       float* __restrict__ out) {
    __shared__ u64 s12[HR * SW2];        // interleaved (a,b); later: scratch
    __shared__ u64 hb12[HR * HBW];       // (mu1,mu2) h-blur
    __shared__ u64 hbsa[HR * HBW];       // (a^2+b^2, a*b) h-blur
    __shared__ float ws[NTHREADS / 32];
    __shared__ double dsum[4];
    __shared__ int s_isLast;

    const int tid = threadIdx.x;
    const int img = blockIdx.z;
    const int tx0 = blockIdx.x * TW;
    const int ty0 = blockIdx.y * TH;

    const float* a = img1 + (size_t)img * (IMGW * IMGH);
    const float* b = img2 + (size_t)img * (IMGW * IMGH);

    const u64 wp[6] = { pack2(W0, W0), pack2(W1, W1), pack2(W2, W2),
                        pack2(W3, W3), pack2(W4, W4), pack2(W5, W5) };

    // ---- load halo tile (both paths div-free, warp-per-row) ----
    const bool interior = (blockIdx.x > 0) & (blockIdx.x < GX - 1) &
                          (blockIdx.y > 0) & (blockIdx.y < GY - 1);
    const int ct = tid & 31;
    const int rt = tid >> 5;
    if (interior) {
        const float* pa = a + (ty0 - HALO) * IMGW + (tx0 - HALO);
        const float* pb = b + (ty0 - HALO) * IMGW + (tx0 - HALO);
#pragma unroll
        for (int rr = 0; rr < 6; rr++) {
            int r = rt + rr * 8;
            if (r < HR) {
                int g = r * IMGW + ct;
                int s = r * SW2 + ct;
#pragma unroll
                for (int cc = 0; cc < 2; cc++) {
                    int c = ct + cc * 32;
                    if (c < HW)
                        s12[s + cc * 32] = pack2(pa[g + cc * 32], pb[g + cc * 32]);
                }
            }
        }
    } else {
#pragma unroll
        for (int rr = 0; rr < 6; rr++) {
            int r = rt + rr * 8;
            if (r < HR) {
                int gy = reflect_idx(ty0 + r - HALO, IMGH);
                const float* ra = a + gy * IMGW;
                const float* rb = b + gy * IMGW;
#pragma unroll
                for (int cc = 0; cc < 2; cc++) {
                    int c = ct + cc * 32;
                    if (c < HW) {
                        int gx = reflect_idx(tx0 + c - HALO, IMGW);
                        s12[r * SW2 + c] = pack2(ra[gx], rb[gx]);
                    }
                }
            }
        }
    }
    __syncthreads();

    // ---- horizontal pass: warps 0-5, each 7 rows x 4 col-groups ----
    {
        const int w    = tid >> 5;
        const int lane = tid & 31;
        const int c0g  = ((lane >> 4) << 1) | ((lane >> 3) & 1);
        const int rl   = lane & 7;
        if (w < 6 && rl < 7) {
            const int r  = w * 7 + rl;        // 0..41
            const int c0 = c0g << 3;          // 0,8,16,24
            const u64* p = s12 + r * SW2 + c0;

            u64 accA[8] = {0, 0, 0, 0, 0, 0, 0, 0};
            u64 accS[8] = {0, 0, 0, 0, 0, 0, 0, 0};
#pragma unroll
            for (int e = 0; e < 18; e++) {
                u64 v = p[e];
                float x, y; unpack2(v, x, y);
                float ab = x * y;
                float ss = fmaf(x, x, y * y);
                u64 sv = pack2(ss, ab);
#pragma unroll
                for (int j = 0; j < 8; j++) {
                    int k = e - j;
                    if (k >= 0 && k <= 10) {
                        fma2(accA[j], v,  wp[WI(k)]);
                        fma2(accS[j], sv, wp[WI(k)]);
                    }
                }
            }
            const int o = r * HBW + c0;
#pragma unroll
            for (int j = 0; j < 8; j++) {
                hb12[o + j] = accA[j];
                hbsa[o + j] = accS[j];
            }
        }
    }
    __syncthreads();

    // ---- vertical pass, channel-split over 8 warps ----
    // warps 0-3: (mu1,mu2) blur for strip sid   -> scratch (mu12, musq)
    // warps 4-7: (ssb,e12) blur for strip sid-4 -> kept in regs; epilogue
    float lsum = 0.f;
    const int tx  = tid & 31;
    const int sid = tid >> 5;
    u64* scratch = s12;                    // s12 is dead after horizontal

    u64 m[8] = {0, 0, 0, 0, 0, 0, 0, 0};
    if (sid < 4) {
        const int r0 = sid << 3;
        const u64* p = hb12 + r0 * HBW + tx;
#pragma unroll
        for (int k = 0; k < 18; k++) {
            u64 h = p[k * HBW];
#pragma unroll
            for (int j = 0; j < 8; j++)
                if (k - j >= 0 && k - j <= 10) fma2(m[j], h, wp[WI(k - j)]);
        }
#pragma unroll
        for (int j = 0; j < 8; j++) {
            float mu1, mu2; unpack2(m[j], mu1, mu2);
            float mu12 = mu1 * mu2;
            float musq = fmaf(mu1, mu1, mu2 * mu2);
            scratch[(r0 + j) * 32 + tx] = pack2(mu12, musq);
        }
    } else {
        const int r0 = (sid - 4) << 3;
        const u64* p = hbsa + r0 * HBW + tx;
#pragma unroll
        for (int k = 0; k < 18; k++) {
            u64 h = p[k * HBW];
#pragma unroll
            for (int j = 0; j < 8; j++)
                if (k - j >= 0 && k - j <= 10) fma2(m[j], h, wp[WI(k - j)]);
        }
    }
    __syncthreads();

    if (sid >= 4) {
        const int r0 = (sid - 4) << 3;
        const float C1 = 1e-4f;
        const float C2 = 9e-4f;
#pragma unroll
        for (int j = 0; j < 8; j++) {
            float ssb, e12; unpack2(m[j], ssb, e12);
            float mu12, musq; unpack2(scratch[(r0 + j) * 32 + tx], mu12, musq);
            float sg12 = e12 - mu12;
            float num = fmaf(2.f, mu12, C1) * fmaf(2.f, sg12, C2);
            float den = (musq + C1) * (ssb - musq + C2);
            float v = __fdividef(num, den);
            v = fminf(fmaxf(v, 0.f), 1.f);
            lsum += v;
        }
    }

    // ---- block reduction ----
#pragma unroll
    for (int off = 16; off > 0; off >>= 1)
        lsum += __shfl_xor_sync(0xffffffff, lsum, off);
    if ((tid & 31) == 0) ws[tid >> 5] = lsum;
    __syncthreads();

    if (tid == 0) {
        float s = 0.f;
#pragma unroll
        for (int i = 0; i < NTHREADS / 32; i++) s += ws[i];
        const int bid = blockIdx.x + GX * (blockIdx.y + GY * blockIdx.z);
        atomicAdd(&g_slots[bid & (NSLOT - 1)], (double)s);
        __threadfence();
        unsigned old = atomicAdd(&g_count, 1u);
        s_isLast = (old == NBLOCKS - 1);
    }
    __syncthreads();

    // ---- last block: finalize + reset for next graph replay ----
    if (s_isLast) {
        double v = 0.0;
        if (tid < NSLOT) v = ((volatile double*)g_slots)[tid];
#pragma unroll
        for (int off = 16; off > 0; off >>= 1)
            v += __shfl_xor_sync(0xffffffff, v, off);
        if (tid < NSLOT && (tid & 31) == 0) dsum[tid >> 5] = v;
        __syncthreads();
        if (tid == 0) {
            double total = dsum[0] + dsum[1] + dsum[2] + dsum[3];
            const double npix = 16.0 * 3.0 * 512.0 * 512.0;
            out[0] = (float)(1.0 - total / npix);
            g_count = 0;
        }
        if (tid < NSLOT) g_slots[tid] = 0.0;
    }
}

extern "C" void kernel_launch(void* const* d_in, const int* in_sizes, int n_in,
                              void* d_out, int out_size) {
    const float* img1 = (const float*)d_in[0];
    const float* img2 = (const float*)d_in[1];
    float* out = (float*)d_out;

    dim3 grid(GX, GY, GZ);
    ssim_fused_kernel<<<grid, NTHREADS>>>(img1, img2, out);
}